// round 4
// baseline (speedup 1.0000x reference)
#include <cuda_runtime.h>
#include <cuda_bf16.h>
#include <cstdint>

#define N_NODES 50000
#define EMB     128
#define R_REL   9
#define S_REL   18            // 2*R
#define NW      19            // 2*R+1
#define N_EDGES 800000
#define E2      (2*N_EDGES)
#define NSEG    (S_REL*N_NODES)   // 900000 (node-major: [i][s])
#define TILES_M 391
#define B_LAYER (NW*EMB)      // 2432

// smem layout (bytes); bf16 row stride 136 elems = 272B (conflict-free for ldmatrix)
#define SROW    272
#define OFF_AHI 0
#define OFF_ALO 34816
#define OFF_BHI 69632
#define OFF_BLO 104448
#define GEMM_DSM 139264

// -------- scratch (device globals) --------
__device__ int   g_cnt2[NSEG];            // counts, [i*18+s]
__device__ float g_alpha2[NSEG];          // suffix products, [i*18+s]
__device__ float g_gamma2[NSEG];          // alpha * raw count
__device__ float g_A[N_NODES];            // full product
__device__ int   g_soff[NSEG + 1];        // segment offsets (sorted by (dest,slot))
__device__ int   g_cur2[NSEG];
__device__ int   g_bsum[1024];
__device__ int   g_boff[1024];
__device__ int   g_rec[E2];               // src node per edge, sorted by (dest,slot)
__device__ float g_H[(size_t)N_NODES * EMB];
__device__ __nv_bfloat16 g_Wthi[2 * NW * EMB * EMB];   // transposed: [l][s][j][k]
__device__ __nv_bfloat16 g_Wtlo[2 * NW * EMB * EMB];
__device__ __nv_bfloat16 g_Bthi[2 * EMB * 32];         // bias chunk: [l][j][k]
__device__ __nv_bfloat16 g_Btlo[2 * EMB * 32];

// ------------------------- PTX helpers -------------------------
__device__ __forceinline__ uint32_t smem_u32(const void* p) {
    uint32_t a;
    asm("{ .reg .u64 t; cvta.to.shared.u64 t, %1; cvt.u32.u64 %0, t; }" : "=r"(a) : "l"(p));
    return a;
}
__device__ __forceinline__ void ldsm_x4(uint32_t* r, uint32_t addr) {
    asm volatile("ldmatrix.sync.aligned.m8n8.x4.shared.b16 {%0,%1,%2,%3}, [%4];"
                 : "=r"(r[0]), "=r"(r[1]), "=r"(r[2]), "=r"(r[3]) : "r"(addr));
}
__device__ __forceinline__ void mma_bf16(float* c, const uint32_t* a, const uint32_t* b) {
    asm volatile("mma.sync.aligned.m16n8k16.row.col.f32.bf16.bf16.f32 "
                 "{%0,%1,%2,%3}, {%4,%5,%6,%7}, {%8,%9}, {%0,%1,%2,%3};"
                 : "+f"(c[0]), "+f"(c[1]), "+f"(c[2]), "+f"(c[3])
                 : "r"(a[0]), "r"(a[1]), "r"(a[2]), "r"(a[3]), "r"(b[0]), "r"(b[1]));
}

// ---------------------------- preprocessing ----------------------------
__global__ void zero_kernel() {
    for (int idx = blockIdx.x * blockDim.x + threadIdx.x; idx < NSEG;
         idx += gridDim.x * blockDim.x) g_cnt2[idx] = 0;
}

__global__ void hist_kernel(const int* __restrict__ ei, const int* __restrict__ et) {
    int idx = blockIdx.x * blockDim.x + threadIdx.x;
    if (idx >= E2) return;
    int dest, s;
    if (idx < N_EDGES) { dest = ei[idx]; s = et[idx]; }
    else { int e = idx - N_EDGES; dest = ei[N_EDGES + e]; s = et[e] + R_REL; }
    atomicAdd(&g_cnt2[dest * S_REL + s], 1);
}

__global__ void alpha_kernel() {
    int i = blockIdx.x * blockDim.x + threadIdx.x;
    if (i >= N_NODES) return;
    int cnt[S_REL];
#pragma unroll
    for (int s = 0; s < S_REL; s++) cnt[s] = g_cnt2[i * S_REL + s];
    float suffix = 1.0f;
#pragma unroll
    for (int k = S_REL - 1; k >= 0; k--) {
        int s = (k >> 1) + R_REL * (k & 1);
        int c = cnt[s];
        float f = 2.0f / (float)(c > 0 ? c : 1);
        suffix *= f;
        g_alpha2[i * S_REL + s] = suffix;
        g_gamma2[i * S_REL + s] = suffix * (float)c;
    }
    g_A[i] = suffix;
}

__global__ void scan1_kernel() {
    __shared__ int wsum[32];
    int b = blockIdx.x, t = threadIdx.x;
    int i = b * 1024 + t;
    int lane = t & 31, w = t >> 5;
    int v = (i < NSEG) ? g_cnt2[i] : 0;
    int val = v;
#pragma unroll
    for (int d = 1; d < 32; d <<= 1) {
        int u = __shfl_up_sync(0xFFFFFFFF, val, d);
        if (lane >= d) val += u;
    }
    if (lane == 31) wsum[w] = val;
    __syncthreads();
    if (w == 0) {
        int x = wsum[lane];
#pragma unroll
        for (int d = 1; d < 32; d <<= 1) {
            int u = __shfl_up_sync(0xFFFFFFFF, x, d);
            if (lane >= d) x += u;
        }
        wsum[lane] = x;
    }
    __syncthreads();
    int incl = val + (w > 0 ? wsum[w - 1] : 0);
    if (i < NSEG) g_soff[i + 1] = incl;
    if (t == 0) g_bsum[b] = wsum[31];
}
__global__ void scan2_kernel(int nb) {
    __shared__ int wsum[32];
    int t = threadIdx.x, lane = t & 31, w = t >> 5;
    int v = (t < nb) ? g_bsum[t] : 0;
    int val = v;
#pragma unroll
    for (int d = 1; d < 32; d <<= 1) {
        int u = __shfl_up_sync(0xFFFFFFFF, val, d);
        if (lane >= d) val += u;
    }
    if (lane == 31) wsum[w] = val;
    __syncthreads();
    if (w == 0) {
        int x = wsum[lane];
#pragma unroll
        for (int d = 1; d < 32; d <<= 1) {
            int u = __shfl_up_sync(0xFFFFFFFF, x, d);
            if (lane >= d) x += u;
        }
        wsum[lane] = x;
    }
    __syncthreads();
    int incl = val + (w > 0 ? wsum[w - 1] : 0);
    if (t < nb) g_boff[t] = incl - v;   // exclusive
}
__global__ void scan3_kernel() {
    int i = blockIdx.x * blockDim.x + threadIdx.x;
    if (i == 0) g_soff[0] = 0;
    if (i >= NSEG) return;
    int off = g_soff[i + 1] + g_boff[i >> 10];
    g_soff[i + 1] = off;
    g_cur2[i] = off - g_cnt2[i];
}

__global__ void scatter_kernel(const int* __restrict__ ei, const int* __restrict__ et) {
    int idx = blockIdx.x * blockDim.x + threadIdx.x;
    if (idx >= E2) return;
    int dest, src, s;
    if (idx < N_EDGES) { dest = ei[idx]; src = ei[N_EDGES + idx]; s = et[idx]; }
    else { int e = idx - N_EDGES; dest = ei[N_EDGES + e]; src = ei[e]; s = et[e] + R_REL; }
    int pos = atomicAdd(&g_cur2[dest * S_REL + s], 1);
    g_rec[pos] = src;
}

// ------------------------ weight / bias conversions ------------------------
__global__ void convw_kernel(const float* __restrict__ w) {
    int idx = blockIdx.x * blockDim.x + threadIdx.x;
    int total = 2 * NW * EMB * EMB;
    if (idx >= total) return;
    int j = idx & 127;
    int k = (idx >> 7) & 127;
    int ls = idx >> 14;
    float v = w[idx];
    __nv_bfloat16 hi = __float2bfloat16(v);
    __nv_bfloat16 lo = __float2bfloat16(v - __bfloat162float(hi));
    int dst = (ls << 14) + j * 128 + k;   // transposed [j][k]
    g_Wthi[dst] = hi;
    g_Wtlo[dst] = lo;
}

// bias B-chunk: Bt[l][j][k] = b[l][k][j] for k<=18, else 0   (j=0..127, k=0..31)
__global__ void convb_kernel(const float* __restrict__ b) {
    int idx = blockIdx.x * blockDim.x + threadIdx.x;
    if (idx >= 2 * EMB * 32) return;
    int k = idx & 31;
    int j = (idx >> 5) & 127;
    int l = idx >> 12;
    float v = (k <= 18) ? b[(l * NW + k) * EMB + j] : 0.0f;
    __nv_bfloat16 hi = __float2bfloat16(v);
    __nv_bfloat16 lo = __float2bfloat16(v - __bfloat162float(hi));
    g_Bthi[idx] = hi;
    g_Btlo[idx] = lo;
}

// --------------------------- fused gather-GEMM ---------------------------
// out[i,:] = sum over 20 K-chunks:
//   chunk s<18 : (alpha_s[i] * sum_{edges(s,i)} X[src]) @ W_s
//   chunk 18   : (A[i] * X[i]) @ W_18
//   chunk 19   : [gamma_0..17, A, 0..] @ Btbias          (32-wide)
// bf16 hi/lo 3-term split; block tile 128(M)x128(N); 8 warps 2(M)x4(N).
__global__ void __launch_bounds__(256) gemmf_kernel(
        const float* __restrict__ X, float* __restrict__ Out,
        int layer, int do_relu) {
    extern __shared__ char dsm[];
    uint32_t sb = smem_u32(dsm);
    int tid = threadIdx.x, wid = tid >> 5, lane = tid & 31;
    int warp_m = wid & 1;
    int warp_n = wid >> 1;

    const __nv_bfloat16* WThi = g_Wthi + (size_t)layer * NW * EMB * EMB;
    const __nv_bfloat16* WTlo = g_Wtlo + (size_t)layer * NW * EMB * EMB;
    const __nv_bfloat16* Bbh  = g_Bthi + layer * EMB * 32;
    const __nv_bfloat16* Bbl  = g_Btlo + layer * EMB * 32;

    // per-thread ldmatrix address components (same mapping as verified R3 kernel)
    uint32_t a_off = (uint32_t)((warp_m * 64 + (lane & 15)) * SROW + ((lane >> 4) * 8) * 2);
    int bm = lane >> 3;
    uint32_t b_row = (uint32_t)(warp_n * 32 + ((bm >> 1) << 3) + (lane & 7));
    uint32_t b_col = (uint32_t)((bm & 1) * 8);

    for (int t = blockIdx.x; t < TILES_M; t += gridDim.x) {
        int m0 = t * 128;

        float acc[4][4][4];
#pragma unroll
        for (int mi = 0; mi < 4; mi++)
#pragma unroll
            for (int ni = 0; ni < 4; ni++)
#pragma unroll
                for (int q = 0; q < 4; q++) acc[mi][ni][q] = 0.f;

        for (int chunk = 0; chunk < 20; chunk++) {
            // ---- fill B ----
            if (chunk < 19) {
                const __nv_bfloat16* bh = WThi + chunk * (EMB * EMB);
                const __nv_bfloat16* bl = WTlo + chunk * (EMB * EMB);
#pragma unroll
                for (int p = 0; p < 8; p++) {
                    int idx = tid + p * 256;
                    int row = idx >> 4, c = idx & 15;
                    uint32_t d = (uint32_t)(row * SROW + c * 16);
                    *(uint4*)(dsm + OFF_BHI + d) = *(const uint4*)(bh + row * 128 + c * 8);
                    *(uint4*)(dsm + OFF_BLO + d) = *(const uint4*)(bl + row * 128 + c * 8);
                }
            } else {
#pragma unroll
                for (int p = 0; p < 2; p++) {
                    int idx = tid + p * 256;
                    int row = idx >> 2, c = idx & 3;
                    uint32_t d = (uint32_t)(row * SROW + c * 16);
                    *(uint4*)(dsm + OFF_BHI + d) = *(const uint4*)(Bbh + row * 32 + c * 8);
                    *(uint4*)(dsm + OFF_BLO + d) = *(const uint4*)(Bbl + row * 32 + c * 8);
                }
            }

            // ---- fill A (gather from L2-resident X) ----
            if (chunk < 18) {
#pragma unroll 1
                for (int q = 0; q < 16; q++) {
                    int r = wid * 16 + q;
                    int i = m0 + r;
                    float4 a4 = make_float4(0.f, 0.f, 0.f, 0.f);
                    float al = 0.f;
                    if (i < N_NODES) {
                        int base = i * S_REL + chunk;
                        int e0 = g_soff[base], e1 = g_soff[base + 1];
                        al = g_alpha2[base];
                        for (int e = e0; e < e1; e++) {
                            int src = g_rec[e];
                            float4 v = *(const float4*)(X + (size_t)src * EMB + lane * 4);
                            a4.x += v.x; a4.y += v.y; a4.z += v.z; a4.w += v.w;
                        }
                    }
                    float f[4] = { al * a4.x, al * a4.y, al * a4.z, al * a4.w };
                    union { __nv_bfloat16 h[4]; uint2 u; } hi, lo;
#pragma unroll
                    for (int c = 0; c < 4; c++) {
                        hi.h[c] = __float2bfloat16(f[c]);
                        lo.h[c] = __float2bfloat16(f[c] - __bfloat162float(hi.h[c]));
                    }
                    uint32_t d = (uint32_t)(r * SROW + lane * 8);
                    *(uint2*)(dsm + OFF_AHI + d) = hi.u;
                    *(uint2*)(dsm + OFF_ALO + d) = lo.u;
                }
            } else if (chunk == 18) {
#pragma unroll 1
                for (int q = 0; q < 16; q++) {
                    int r = wid * 16 + q;
                    int i = m0 + r;
                    float f[4] = { 0.f, 0.f, 0.f, 0.f };
                    if (i < N_NODES) {
                        float Ai = g_A[i];
                        float4 v = *(const float4*)(X + (size_t)i * EMB + lane * 4);
                        f[0] = Ai * v.x; f[1] = Ai * v.y; f[2] = Ai * v.z; f[3] = Ai * v.w;
                    }
                    union { __nv_bfloat16 h[4]; uint2 u; } hi, lo;
#pragma unroll
                    for (int c = 0; c < 4; c++) {
                        hi.h[c] = __float2bfloat16(f[c]);
                        lo.h[c] = __float2bfloat16(f[c] - __bfloat162float(hi.h[c]));
                    }
                    uint32_t d = (uint32_t)(r * SROW + lane * 8);
                    *(uint2*)(dsm + OFF_AHI + d) = hi.u;
                    *(uint2*)(dsm + OFF_ALO + d) = lo.u;
                }
            } else {
                // bias chunk: cols 0..31 per row; col = lane
#pragma unroll 1
                for (int q = 0; q < 16; q++) {
                    int r = wid * 16 + q;
                    int i = m0 + r;
                    float v = 0.f;
                    if (i < N_NODES) {
                        if (lane < S_REL)      v = g_gamma2[i * S_REL + lane];
                        else if (lane == S_REL) v = g_A[i];
                    }
                    __nv_bfloat16 hi = __float2bfloat16(v);
                    __nv_bfloat16 lo = __float2bfloat16(v - __bfloat162float(hi));
                    uint32_t d = (uint32_t)(r * SROW + lane * 2);
                    *(__nv_bfloat16*)(dsm + OFF_AHI + d) = hi;
                    *(__nv_bfloat16*)(dsm + OFF_ALO + d) = lo;
                }
            }
            __syncthreads();

            // ---- MMA over this chunk ----
            int ksteps = (chunk < 19) ? 8 : 2;
            for (int ks = 0; ks < ksteps; ks++) {
                uint32_t k2 = (uint32_t)(ks * 32);
                uint32_t Ah[4][4], Al[4][4];
#pragma unroll
                for (int mi = 0; mi < 4; mi++) {
                    uint32_t ad = sb + OFF_AHI + a_off + (uint32_t)(mi * 16 * SROW) + k2;
                    ldsm_x4(Ah[mi], ad);
                    ldsm_x4(Al[mi], ad + (OFF_ALO - OFF_AHI));
                }
                uint32_t Bh[4][2], Bl[4][2];
#pragma unroll
                for (int nj = 0; nj < 2; nj++) {
                    uint32_t bd = sb + OFF_BHI + (b_row + nj * 16) * SROW + b_col * 2 + k2;
                    uint32_t r4[4];
                    ldsm_x4(r4, bd);
                    Bh[nj * 2][0] = r4[0]; Bh[nj * 2][1] = r4[1];
                    Bh[nj * 2 + 1][0] = r4[2]; Bh[nj * 2 + 1][1] = r4[3];
                    ldsm_x4(r4, bd + (OFF_BLO - OFF_BHI));
                    Bl[nj * 2][0] = r4[0]; Bl[nj * 2][1] = r4[1];
                    Bl[nj * 2 + 1][0] = r4[2]; Bl[nj * 2 + 1][1] = r4[3];
                }
#pragma unroll
                for (int mi = 0; mi < 4; mi++)
#pragma unroll
                    for (int ni = 0; ni < 4; ni++) {
                        mma_bf16(acc[mi][ni], Ah[mi], Bh[ni]);
                        mma_bf16(acc[mi][ni], Ah[mi], Bl[ni]);
                        mma_bf16(acc[mi][ni], Al[mi], Bh[ni]);
                    }
            }
            __syncthreads();
        }

        // ---- epilogue: write Out (optionally relu) ----
        int rbase = m0 + warp_m * 64 + (lane >> 2);
        int cbase = warp_n * 32 + (lane & 3) * 2;
#pragma unroll
        for (int mi = 0; mi < 4; mi++) {
            int r = rbase + mi * 16;
#pragma unroll
            for (int ni = 0; ni < 4; ni++) {
                int c = cbase + ni * 8;
                float2 v0 = make_float2(acc[mi][ni][0], acc[mi][ni][1]);
                float2 v1 = make_float2(acc[mi][ni][2], acc[mi][ni][3]);
                if (do_relu) {
                    v0.x = fmaxf(v0.x, 0.f); v0.y = fmaxf(v0.y, 0.f);
                    v1.x = fmaxf(v1.x, 0.f); v1.y = fmaxf(v1.y, 0.f);
                }
                if (r < N_NODES)
                    *(float2*)(Out + (size_t)r * EMB + c) = v0;
                if (r + 8 < N_NODES)
                    *(float2*)(Out + (size_t)(r + 8) * EMB + c) = v1;
            }
        }
    }
}

// ------------------------------ launch ---------------------------------
extern "C" void kernel_launch(void* const* d_in, const int* in_sizes, int n_in,
                              void* d_out, int out_size) {
    const int*   ei  = (const int*)d_in[0];     // [2, E]
    const int*   et  = (const int*)d_in[1];     // [E]
    const float* emb = (const float*)d_in[2];   // [N, 128]
    const float* w   = (const float*)d_in[3];   // [2, 19, 128, 128]
    const float* b   = (const float*)d_in[4];   // [2, 19, 128]
    float* out = (float*)d_out;

    float* hptr = nullptr;
    cudaGetSymbolAddress((void**)&hptr, g_H);

    cudaFuncSetAttribute(gemmf_kernel,
                         cudaFuncAttributeMaxDynamicSharedMemorySize, GEMM_DSM);

    zero_kernel<<<512, 256>>>();
    hist_kernel<<<(E2 + 255) / 256, 256>>>(ei, et);
    alpha_kernel<<<(N_NODES + 255) / 256, 256>>>();
    int nb = (NSEG + 1023) / 1024;   // 879
    scan1_kernel<<<nb, 1024>>>();
    scan2_kernel<<<1, 1024>>>(nb);
    scan3_kernel<<<(NSEG + 255) / 256, 256>>>();
    scatter_kernel<<<(E2 + 255) / 256, 256>>>(ei, et);

    convw_kernel<<<(2 * NW * EMB * EMB + 255) / 256, 256>>>(w);
    convb_kernel<<<(2 * EMB * 32 + 255) / 256, 256>>>(b);

    // layer 0: emb -> H (relu)
    gemmf_kernel<<<148, 256, GEMM_DSM>>>(emb, hptr, 0, 1);
    // layer 1: H -> out
    gemmf_kernel<<<148, 256, GEMM_DSM>>>(hptr, out, 1, 0);
}

// round 5
// speedup vs baseline: 1.9295x; 1.9295x over previous
#include <cuda_runtime.h>
#include <cuda_bf16.h>
#include <cstdint>

#define N_NODES 50000
#define EMB     128
#define R_REL   9
#define S_REL   18            // 2*R
#define NW      19            // 2*R+1
#define N_EDGES 800000
#define E2      (2*N_EDGES)
#define NSEG    (S_REL*N_NODES)   // 900000 (node-major: [i][s])
#define TILES_M 391
#define KTOT    2496          // 19*128 + 64 (bias block padded to 64)
#define NCH     39            // K sub-chunks of 64

// smem: 4 arrays (Ahi,Alo,Bhi,Blo) x 2 stages; 128 rows x 64 bf16, row stride 144B
#define SROW2   144
#define ATILE2  18432          // 128*144
#define STAGE_SZ (4*ATILE2)    // 73728
#define OFF_AHI 0
#define OFF_ALO ATILE2
#define OFF_BHI (2*ATILE2)
#define OFF_BLO (3*ATILE2)
#define GEMM_DSM (2*STAGE_SZ)  // 147456

// -------- scratch (device globals) --------
__device__ int   g_cnt2[NSEG];
__device__ float g_alpha2[NSEG];
__device__ float g_gamma2[NSEG];
__device__ float g_A[N_NODES];
__device__ int   g_soff[NSEG + 1];
__device__ int   g_cur2[NSEG];
__device__ int   g_bsum[1024];
__device__ int   g_boff[1024];
__device__ int   g_rec[E2];               // src node, sorted by (dest, slot)
__device__ float g_H[(size_t)N_NODES * EMB];
__device__ __nv_bfloat16 g_Ahi[(size_t)N_NODES * KTOT];   // ~250 MB
__device__ __nv_bfloat16 g_Alo[(size_t)N_NODES * KTOT];   // ~250 MB
__device__ __nv_bfloat16 g_Wthi[2 * EMB * KTOT];          // [l][j][k]
__device__ __nv_bfloat16 g_Wtlo[2 * EMB * KTOT];

// ------------------------- PTX helpers -------------------------
__device__ __forceinline__ uint32_t smem_u32(const void* p) {
    uint32_t a;
    asm("{ .reg .u64 t; cvta.to.shared.u64 t, %1; cvt.u32.u64 %0, t; }" : "=r"(a) : "l"(p));
    return a;
}
__device__ __forceinline__ void cp_async16(uint32_t dst, const void* src, int srcsize) {
    asm volatile("cp.async.cg.shared.global [%0], [%1], 16, %2;"
                 :: "r"(dst), "l"(src), "r"(srcsize) : "memory");
}
#define CP_COMMIT() asm volatile("cp.async.commit_group;" ::: "memory")
#define CP_WAIT1()  asm volatile("cp.async.wait_group 1;" ::: "memory")
#define CP_WAIT0()  asm volatile("cp.async.wait_group 0;" ::: "memory")

__device__ __forceinline__ void ldsm_x4(uint32_t* r, uint32_t addr) {
    asm volatile("ldmatrix.sync.aligned.m8n8.x4.shared.b16 {%0,%1,%2,%3}, [%4];"
                 : "=r"(r[0]), "=r"(r[1]), "=r"(r[2]), "=r"(r[3]) : "r"(addr));
}
__device__ __forceinline__ void mma_bf16(float* c, const uint32_t* a, const uint32_t* b) {
    asm volatile("mma.sync.aligned.m16n8k16.row.col.f32.bf16.bf16.f32 "
                 "{%0,%1,%2,%3}, {%4,%5,%6,%7}, {%8,%9}, {%0,%1,%2,%3};"
                 : "+f"(c[0]), "+f"(c[1]), "+f"(c[2]), "+f"(c[3])
                 : "r"(a[0]), "r"(a[1]), "r"(a[2]), "r"(a[3]), "r"(b[0]), "r"(b[1]));
}

// ---------------------------- preprocessing ----------------------------
__global__ void zero_kernel() {
    for (int idx = blockIdx.x * blockDim.x + threadIdx.x; idx < NSEG;
         idx += gridDim.x * blockDim.x) g_cnt2[idx] = 0;
}

__global__ void hist_kernel(const int* __restrict__ ei, const int* __restrict__ et) {
    int idx = blockIdx.x * blockDim.x + threadIdx.x;
    if (idx >= E2) return;
    int dest, s;
    if (idx < N_EDGES) { dest = ei[idx]; s = et[idx]; }
    else { int e = idx - N_EDGES; dest = ei[N_EDGES + e]; s = et[e] + R_REL; }
    atomicAdd(&g_cnt2[dest * S_REL + s], 1);
}

__global__ void alpha_kernel() {
    int i = blockIdx.x * blockDim.x + threadIdx.x;
    if (i >= N_NODES) return;
    int cnt[S_REL];
#pragma unroll
    for (int s = 0; s < S_REL; s++) cnt[s] = g_cnt2[i * S_REL + s];
    float suffix = 1.0f;
#pragma unroll
    for (int k = S_REL - 1; k >= 0; k--) {
        int s = (k >> 1) + R_REL * (k & 1);
        int c = cnt[s];
        float f = 2.0f / (float)(c > 0 ? c : 1);
        suffix *= f;
        g_alpha2[i * S_REL + s] = suffix;
        g_gamma2[i * S_REL + s] = suffix * (float)c;
    }
    g_A[i] = suffix;
}

__global__ void scan1_kernel() {
    __shared__ int wsum[32];
    int b = blockIdx.x, t = threadIdx.x;
    int i = b * 1024 + t;
    int lane = t & 31, w = t >> 5;
    int v = (i < NSEG) ? g_cnt2[i] : 0;
    int val = v;
#pragma unroll
    for (int d = 1; d < 32; d <<= 1) {
        int u = __shfl_up_sync(0xFFFFFFFF, val, d);
        if (lane >= d) val += u;
    }
    if (lane == 31) wsum[w] = val;
    __syncthreads();
    if (w == 0) {
        int x = wsum[lane];
#pragma unroll
        for (int d = 1; d < 32; d <<= 1) {
            int u = __shfl_up_sync(0xFFFFFFFF, x, d);
            if (lane >= d) x += u;
        }
        wsum[lane] = x;
    }
    __syncthreads();
    int incl = val + (w > 0 ? wsum[w - 1] : 0);
    if (i < NSEG) g_soff[i + 1] = incl;
    if (t == 0) g_bsum[b] = wsum[31];
}
__global__ void scan2_kernel(int nb) {
    __shared__ int wsum[32];
    int t = threadIdx.x, lane = t & 31, w = t >> 5;
    int v = (t < nb) ? g_bsum[t] : 0;
    int val = v;
#pragma unroll
    for (int d = 1; d < 32; d <<= 1) {
        int u = __shfl_up_sync(0xFFFFFFFF, val, d);
        if (lane >= d) val += u;
    }
    if (lane == 31) wsum[w] = val;
    __syncthreads();
    if (w == 0) {
        int x = wsum[lane];
#pragma unroll
        for (int d = 1; d < 32; d <<= 1) {
            int u = __shfl_up_sync(0xFFFFFFFF, x, d);
            if (lane >= d) x += u;
        }
        wsum[lane] = x;
    }
    __syncthreads();
    int incl = val + (w > 0 ? wsum[w - 1] : 0);
    if (t < nb) g_boff[t] = incl - v;   // exclusive
}
__global__ void scan3_kernel() {
    int i = blockIdx.x * blockDim.x + threadIdx.x;
    if (i == 0) g_soff[0] = 0;
    if (i >= NSEG) return;
    int off = g_soff[i + 1] + g_boff[i >> 10];
    g_soff[i + 1] = off;
    g_cur2[i] = off - g_cnt2[i];
}

__global__ void scatter_kernel(const int* __restrict__ ei, const int* __restrict__ et) {
    int idx = blockIdx.x * blockDim.x + threadIdx.x;
    if (idx >= E2) return;
    int dest, src, s;
    if (idx < N_EDGES) { dest = ei[idx]; src = ei[N_EDGES + idx]; s = et[idx]; }
    else { int e = idx - N_EDGES; dest = ei[N_EDGES + e]; src = ei[e]; s = et[e] + R_REL; }
    int pos = atomicAdd(&g_cur2[dest * S_REL + s], 1);
    g_rec[pos] = src;
}

// ---------------- weight conversion: Wt[l][j][k], K = 2496 ----------------
// k < 2432        : W[l][k/128][k%128][j]
// 2432 <= k < 2451: b[l][k-2432][j]      (bias block, 19 cols)
// else            : 0
__global__ void convw_kernel(const float* __restrict__ w, const float* __restrict__ b) {
    int idx = blockIdx.x * blockDim.x + threadIdx.x;
    int total = 2 * EMB * KTOT;
    if (idx >= total) return;
    int k = idx % KTOT;
    int j = (idx / KTOT) & 127;
    int l = idx / (KTOT * EMB);
    float v = 0.0f;
    if (k < 2432) {
        int s = k >> 7, kk = k & 127;
        v = w[(((size_t)l * NW + s) * EMB + kk) * EMB + j];
    } else if (k < 2432 + NW) {
        v = b[((size_t)l * NW + (k - 2432)) * EMB + j];
    }
    __nv_bfloat16 hi = __float2bfloat16(v);
    __nv_bfloat16 lo = __float2bfloat16(v - __bfloat162float(hi));
    g_Wthi[idx] = hi;
    g_Wtlo[idx] = lo;
}

// ---------------- aggregation: build Ahat row per node ----------------
// chunk s<18 : alpha_s[i] * sum_{edges of (i,s)} X[src]     (cols s*128..)
// chunk 18   : A[i] * X[i]                                   (cols 2304..)
// bias block : cols 2432+q: q<18 -> gamma, q==18 -> A[i], else 0
__global__ void __launch_bounds__(256) agg_kernel(const float* __restrict__ X) {
    int warp = (blockIdx.x << 3) + (threadIdx.x >> 5);
    if (warp >= N_NODES) return;
    int i = warp;
    int lane = threadIdx.x & 31;
    int fo = lane << 2;
    size_t arow = (size_t)i * KTOT;

#pragma unroll 1
    for (int s = 0; s < S_REL; s++) {
        int sb = i * S_REL + s;
        int e0 = g_soff[sb], e1 = g_soff[sb + 1];
        float al = g_alpha2[sb];
        float4 a = make_float4(0.f, 0.f, 0.f, 0.f);
        for (int e = e0; e < e1; e++) {
            int src = g_rec[e];
            float4 v = *(const float4*)(X + (size_t)src * EMB + fo);
            a.x += v.x; a.y += v.y; a.z += v.z; a.w += v.w;
        }
        float f[4] = { al * a.x, al * a.y, al * a.z, al * a.w };
        union { __nv_bfloat16 h[4]; uint2 u; } hi, lo;
#pragma unroll
        for (int c = 0; c < 4; c++) {
            hi.h[c] = __float2bfloat16(f[c]);
            lo.h[c] = __float2bfloat16(f[c] - __bfloat162float(hi.h[c]));
        }
        *(uint2*)(g_Ahi + arow + s * 128 + fo) = hi.u;
        *(uint2*)(g_Alo + arow + s * 128 + fo) = lo.u;
    }
    {   // self slot
        float Ai = g_A[i];
        float4 v = *(const float4*)(X + (size_t)i * EMB + fo);
        float f[4] = { Ai * v.x, Ai * v.y, Ai * v.z, Ai * v.w };
        union { __nv_bfloat16 h[4]; uint2 u; } hi, lo;
#pragma unroll
        for (int c = 0; c < 4; c++) {
            hi.h[c] = __float2bfloat16(f[c]);
            lo.h[c] = __float2bfloat16(f[c] - __bfloat162float(hi.h[c]));
        }
        *(uint2*)(g_Ahi + arow + S_REL * 128 + fo) = hi.u;
        *(uint2*)(g_Alo + arow + S_REL * 128 + fo) = lo.u;
    }
    {   // bias block: 64 cols, 2 per lane
        union { __nv_bfloat16 h[2]; uint u; } hi, lo;
#pragma unroll
        for (int c = 0; c < 2; c++) {
            int q = lane * 2 + c;
            float v = 0.f;
            if (q < S_REL)       v = g_gamma2[i * S_REL + q];
            else if (q == S_REL) v = g_A[i];
            hi.h[c] = __float2bfloat16(v);
            lo.h[c] = __float2bfloat16(v - __bfloat162float(hi.h[c]));
        }
        *(uint*)(g_Ahi + arow + 2432 + lane * 2) = hi.u;
        *(uint*)(g_Alo + arow + 2432 + lane * 2) = lo.u;
    }
}

// --------------------------- streaming GEMM ---------------------------
// Out[M=50000, 128] = Ahat[M, 2496] @ Wt^T  (bf16 hi/lo 3-term split)
// Tile 128(M)x128(N); K pipelined in 39 sub-chunks of 64; 2-stage cp.async.
__device__ __forceinline__ void fill_stage(
        uint32_t sbase, int k0, int m0, int tid,
        const __nv_bfloat16* __restrict__ Wh, const __nv_bfloat16* __restrict__ Wl) {
#pragma unroll
    for (int p = 0; p < 4; p++) {
        int idx = tid + p * 256;          // 0..1023
        int row = idx >> 3, c = idx & 7;  // 8 x 16B per 128B row
        uint32_t d = (uint32_t)(row * SROW2 + c * 16);
        int gm = m0 + row;
        int ok = gm < N_NODES;
        size_t asrc = (size_t)(ok ? gm : 0) * KTOT + k0 + c * 8;
        int sz = ok ? 16 : 0;
        cp_async16(sbase + OFF_AHI + d, g_Ahi + asrc, sz);
        cp_async16(sbase + OFF_ALO + d, g_Alo + asrc, sz);
        size_t bsrc = (size_t)row * KTOT + k0 + c * 8;
        cp_async16(sbase + OFF_BHI + d, Wh + bsrc, 16);
        cp_async16(sbase + OFF_BLO + d, Wl + bsrc, 16);
    }
}

__global__ void __launch_bounds__(256) gemm6_kernel(float* __restrict__ Out,
                                                    int layer, int do_relu) {
    extern __shared__ char dsm[];
    uint32_t sb = smem_u32(dsm);
    int tid = threadIdx.x, wid = tid >> 5, lane = tid & 31;
    int warp_m = wid & 1;
    int warp_n = wid >> 1;

    const __nv_bfloat16* Wh = g_Wthi + (size_t)layer * EMB * KTOT;
    const __nv_bfloat16* Wl = g_Wtlo + (size_t)layer * EMB * KTOT;

    uint32_t a_off = (uint32_t)((warp_m * 64 + (lane & 15)) * SROW2 + ((lane >> 4) * 8) * 2);
    int bm = lane >> 3;
    uint32_t b_row = (uint32_t)(warp_n * 32 + ((bm >> 1) << 3) + (lane & 7));
    uint32_t b_col = (uint32_t)((bm & 1) * 8);

    for (int t = blockIdx.x; t < TILES_M; t += gridDim.x) {
        int m0 = t * 128;

        float acc[4][4][4];
#pragma unroll
        for (int mi = 0; mi < 4; mi++)
#pragma unroll
            for (int ni = 0; ni < 4; ni++)
#pragma unroll
                for (int q = 0; q < 4; q++) acc[mi][ni][q] = 0.f;

        fill_stage(sb, 0, m0, tid, Wh, Wl);
        CP_COMMIT();

        for (int u = 0; u < NCH; u++) {
            if (u + 1 < NCH) {
                fill_stage(sb + ((u + 1) & 1) * STAGE_SZ, (u + 1) * 64, m0, tid, Wh, Wl);
                CP_COMMIT();
                CP_WAIT1();
            } else {
                CP_WAIT0();
            }
            __syncthreads();

            uint32_t st = sb + (u & 1) * STAGE_SZ;
#pragma unroll
            for (int ks = 0; ks < 4; ks++) {
                uint32_t k2 = (uint32_t)(ks * 32);
                uint32_t Ah[4][4], Al[4][4];
#pragma unroll
                for (int mi = 0; mi < 4; mi++) {
                    uint32_t ad = st + OFF_AHI + a_off + (uint32_t)(mi * 16 * SROW2) + k2;
                    ldsm_x4(Ah[mi], ad);
                    ldsm_x4(Al[mi], ad + (OFF_ALO - OFF_AHI));
                }
                uint32_t Bh[4][2], Bl[4][2];
#pragma unroll
                for (int nj = 0; nj < 2; nj++) {
                    uint32_t bd = st + OFF_BHI + (b_row + nj * 16) * SROW2 + b_col * 2 + k2;
                    uint32_t r4[4];
                    ldsm_x4(r4, bd);
                    Bh[nj * 2][0] = r4[0]; Bh[nj * 2][1] = r4[1];
                    Bh[nj * 2 + 1][0] = r4[2]; Bh[nj * 2 + 1][1] = r4[3];
                    ldsm_x4(r4, bd + (OFF_BLO - OFF_BHI));
                    Bl[nj * 2][0] = r4[0]; Bl[nj * 2][1] = r4[1];
                    Bl[nj * 2 + 1][0] = r4[2]; Bl[nj * 2 + 1][1] = r4[3];
                }
#pragma unroll
                for (int mi = 0; mi < 4; mi++)
#pragma unroll
                    for (int ni = 0; ni < 4; ni++) {
                        mma_bf16(acc[mi][ni], Ah[mi], Bh[ni]);
                        mma_bf16(acc[mi][ni], Ah[mi], Bl[ni]);
                        mma_bf16(acc[mi][ni], Al[mi], Bh[ni]);
                    }
            }
            __syncthreads();
        }

        // epilogue
        int rbase = m0 + warp_m * 64 + (lane >> 2);
        int cbase = warp_n * 32 + (lane & 3) * 2;
#pragma unroll
        for (int mi = 0; mi < 4; mi++) {
            int r = rbase + mi * 16;
#pragma unroll
            for (int ni = 0; ni < 4; ni++) {
                int c = cbase + ni * 8;
                float2 v0 = make_float2(acc[mi][ni][0], acc[mi][ni][1]);
                float2 v1 = make_float2(acc[mi][ni][2], acc[mi][ni][3]);
                if (do_relu) {
                    v0.x = fmaxf(v0.x, 0.f); v0.y = fmaxf(v0.y, 0.f);
                    v1.x = fmaxf(v1.x, 0.f); v1.y = fmaxf(v1.y, 0.f);
                }
                if (r < N_NODES)
                    *(float2*)(Out + (size_t)r * EMB + c) = v0;
                if (r + 8 < N_NODES)
                    *(float2*)(Out + (size_t)(r + 8) * EMB + c) = v1;
            }
        }
    }
}

// ------------------------------ launch ---------------------------------
extern "C" void kernel_launch(void* const* d_in, const int* in_sizes, int n_in,
                              void* d_out, int out_size) {
    const int*   ei  = (const int*)d_in[0];     // [2, E]
    const int*   et  = (const int*)d_in[1];     // [E]
    const float* emb = (const float*)d_in[2];   // [N, 128]
    const float* w   = (const float*)d_in[3];   // [2, 19, 128, 128]
    const float* b   = (const float*)d_in[4];   // [2, 19, 128]
    float* out = (float*)d_out;

    float* hptr = nullptr;
    cudaGetSymbolAddress((void**)&hptr, g_H);

    cudaFuncSetAttribute(gemm6_kernel,
                         cudaFuncAttributeMaxDynamicSharedMemorySize, GEMM_DSM);

    zero_kernel<<<512, 256>>>();
    hist_kernel<<<(E2 + 255) / 256, 256>>>(ei, et);
    alpha_kernel<<<(N_NODES + 255) / 256, 256>>>();
    int nb = (NSEG + 1023) / 1024;   // 879
    scan1_kernel<<<nb, 1024>>>();
    scan2_kernel<<<1, 1024>>>(nb);
    scan3_kernel<<<(NSEG + 255) / 256, 256>>>();
    scatter_kernel<<<(E2 + 255) / 256, 256>>>(ei, et);
    convw_kernel<<<(2 * EMB * KTOT + 255) / 256, 256>>>(w, b);

    int agrid = (N_NODES + 7) / 8;

    // layer 0: emb -> H (relu)
    agg_kernel<<<agrid, 256>>>(emb);
    gemm6_kernel<<<TILES_M, 256, GEMM_DSM>>>(hptr, 0, 1);
    // layer 1: H -> out
    agg_kernel<<<agrid, 256>>>(hptr);
    gemm6_kernel<<<TILES_M, 256, GEMM_DSM>>>(out, 1, 0);
}